// round 14
// baseline (speedup 1.0000x reference)
#include <cuda_runtime.h>
#include <cstdint>

// ---------------------------------------------------------------------------
// LinearFlow: out[t,n,i] = sum_j expm(t_k * A)[i,j] * x[n,j]
//   A = 0.5*((M+M0) - (M+M0)^T), 8x8 skew-symmetric, ||tA|| <~ 0.15
//
// Fused kernel, R13: TMA bulk-store epilogue (R11 with staging-buffer size
// bug fixed: tile is 8 KB = 512 ulonglong2, buffer was declared 256).
//   - Taylor expm prologue (register-resident rows, no syncs in loop)
//   - i-pair f32x2 compute: accumulators ARE the output float4s
//   - per-t output tile (256 rows x 32 B = 8 KB, contiguous in gmem) staged
//     in double-buffered smem via STS.128, drained by ONE thread via
//     cp.async.bulk.global.shared (async proxy). Removes all STG wavefronts
//     from L1 and store backpressure from warps.
// ---------------------------------------------------------------------------

#define MS        8
#define TB_T      16     // t-values per block
#define ROWS_B    256    // n-rows per block (8 warps x 32 rows)
#define THREADS   256
#define KTERMS    10     // Taylor order; ||tA||<=0.15 -> error ~1e-17
#define TILE_B    (ROWS_B * MS * 4)   // 8192 bytes per t-plane tile

// ---- f32x2 helpers ---------------------------------------------------------
__device__ __forceinline__ unsigned long long pack2(float lo, float hi) {
    unsigned long long r;
    asm("mov.b64 %0, {%1, %2};" : "=l"(r) : "f"(lo), "f"(hi));
    return r;
}
__device__ __forceinline__ unsigned long long fma2(unsigned long long a,
                                                   unsigned long long b,
                                                   unsigned long long c) {
    unsigned long long d;
    asm("fma.rn.f32x2 %0, %1, %2, %3;" : "=l"(d) : "l"(a), "l"(b), "l"(c));
    return d;
}
__device__ __forceinline__ uint32_t smem_u32(const void* p) {
    uint32_t a;
    asm("{ .reg .u64 t; cvta.to.shared.u64 t, %1; cvt.u32.u64 %0, t; }"
        : "=r"(a) : "l"(p));
    return a;
}

// ---------------------------------------------------------------------------
__global__ void __launch_bounds__(THREADS, 5)
fused_kernel(const float* __restrict__ x,
             const float* __restrict__ t,
             const float* __restrict__ M,
             const float* __restrict__ M0,
             float* __restrict__ out,
             int N) {
    __shared__ float sAskew[64];                               // unscaled skew(A)
    __shared__ unsigned long long sE[TB_T * 32];               // 4 KB packed E
    __shared__ __align__(128) ulonglong2 sOut[2][ROWS_B * 2];  // 2 x 8 KB tiles

    const int tid   = threadIdx.x;
    const int tbase = blockIdx.y * TB_T;

    // ---- stage A_skew ----
    if (tid < 64) {
        const int i = tid >> 3, j = tid & 7;
        sAskew[tid] = 0.5f * ((M[i * 8 + j] + M0[i * 8 + j]) -
                              (M[j * 8 + i] + M0[j * 8 + i]));
    }
    __syncthreads();

    // ---- load x rows ----
    const int warp = tid >> 5;
    const int lane = tid & 31;
    const int h    = lane & 1;
    const int rb   = blockIdx.x * ROWS_B;
    const int lrA  = warp * 32 + (lane >> 1);   // local row A in [0,240)
    const int rowA = rb + lrA;
    const int rowB = rowA + 16;

    unsigned long long xA[8], xB[8];
    {
        const float4* xpA = reinterpret_cast<const float4*>(x) + (size_t)rowA * 2;
        const float4* xpB = reinterpret_cast<const float4*>(x) + (size_t)rowB * 2;
        float4 a0 = xpA[0], a1 = xpA[1], b0 = xpB[0], b1 = xpB[1];
        xA[0] = pack2(a0.x, a0.x);  xA[1] = pack2(a0.y, a0.y);
        xA[2] = pack2(a0.z, a0.z);  xA[3] = pack2(a0.w, a0.w);
        xA[4] = pack2(a1.x, a1.x);  xA[5] = pack2(a1.y, a1.y);
        xA[6] = pack2(a1.z, a1.z);  xA[7] = pack2(a1.w, a1.w);
        xB[0] = pack2(b0.x, b0.x);  xB[1] = pack2(b0.y, b0.y);
        xB[2] = pack2(b0.z, b0.z);  xB[3] = pack2(b0.w, b0.w);
        xB[4] = pack2(b1.x, b1.x);  xB[5] = pack2(b1.y, b1.y);
        xB[6] = pack2(b1.z, b1.z);  xB[7] = pack2(b1.w, b1.w);
    }

    // ---- Taylor expm prologue: thread (tl, i) owns row i for t-slot tl ----
    if (tid < TB_T * 8) {
        const int tl = tid >> 3;
        const int i  = tid & 7;
        const float tv = t[tbase + tl];

        float r[8], acc[8];
        #pragma unroll
        for (int j = 0; j < 8; j++) {
            r[j]   = tv * sAskew[i * 8 + j];
            acc[j] = ((i == j) ? 1.0f : 0.0f) + r[j];
        }
        #pragma unroll
        for (int k = 2; k <= KTERMS; k++) {
            float tmp[8];
            #pragma unroll
            for (int j = 0; j < 8; j++) {
                float c = 0.0f;
                #pragma unroll
                for (int m = 0; m < 8; m++)
                    c = fmaf(r[m], sAskew[m * 8 + j], c);
                tmp[j] = c;
            }
            const float s = tv * (1.0f / (float)k);
            #pragma unroll
            for (int j = 0; j < 8; j++) {
                r[j] = tmp[j] * s;
                acc[j] += r[j];
            }
        }
        // packed: float slot = (tl*32 + j*4 + (i>>1))*2 + (i&1)
        float* fE = reinterpret_cast<float*>(sE);
        #pragma unroll
        for (int j = 0; j < 8; j++)
            fE[(tl * 32 + j * 4 + (i >> 1)) * 2 + (i & 1)] = acc[j];
    }

    // ---- main loop: compute t-plane tile -> smem -> bulk store ----
    const unsigned long long* eB = sE + 2 * h;          // p-offset = 2h
    const int sIdxA = lrA * 2 + h;                      // ulonglong2 idx, <= 479
                                                        // rowB idx = sIdxA+32 <= 511

    // gmem byte address of this block's tile for t-plane tbase
    const char* gdst0 = reinterpret_cast<const char*>(out)
                      + ((size_t)tbase * N + rb) * (MS * 4);
    const size_t gstep = (size_t)N * (MS * 4);          // bytes per t-plane

    __syncthreads();   // sE ready

    for (int tl = 0; tl < TB_T; tl++) {
        const int buf = tl & 1;

        // compute accumulators (independent of staging buffers)
        const unsigned long long* e = eB + tl * 32;
        unsigned long long oA01 = 0ull, oA23 = 0ull, oB01 = 0ull, oB23 = 0ull;
        #pragma unroll
        for (int j = 0; j < 8; j++) {
            ulonglong2 ep = *reinterpret_cast<const ulonglong2*>(e + j * 4);
            oA01 = fma2(ep.x, xA[j], oA01);
            oA23 = fma2(ep.y, xA[j], oA23);
            oB01 = fma2(ep.x, xB[j], oB01);
            oB23 = fma2(ep.y, xB[j], oB23);
        }

        // ensure the bulk store issued at tl-2 (same buffer) has completed
        if (tid == 0)
            asm volatile("cp.async.bulk.wait_group 1;" ::: "memory");
        __syncthreads();

        // stage tile: two STS.128 per thread, conflict-free, 512 B/warp-op
        ulonglong2 vA; vA.x = oA01; vA.y = oA23;
        ulonglong2 vB; vB.x = oB01; vB.y = oB23;
        sOut[buf][sIdxA]      = vA;
        sOut[buf][sIdxA + 32] = vB;                     // rowB = rowA+16
        __syncthreads();

        // one thread drains the 8 KB tile through the async proxy
        if (tid == 0) {
            asm volatile("fence.proxy.async;" ::: "memory");
            const uint32_t sa = smem_u32(&sOut[buf][0]);
            const char* ga = gdst0 + (size_t)tl * gstep;
            asm volatile(
                "cp.async.bulk.global.shared::cta.bulk_group [%0], [%1], %2;"
                :: "l"(ga), "r"(sa), "r"(TILE_B) : "memory");
            asm volatile("cp.async.bulk.commit_group;" ::: "memory");
        }
    }

    // drain remaining bulk stores before exit (smem must stay live)
    if (tid == 0)
        asm volatile("cp.async.bulk.wait_group 0;" ::: "memory");
    __syncthreads();
}

// ---------------------------------------------------------------------------
extern "C" void kernel_launch(void* const* d_in, const int* in_sizes, int n_in,
                              void* d_out, int out_size) {
    const float* x  = (const float*)d_in[0];   // [N, 8]
    const float* t  = (const float*)d_in[1];   // [T]
    const float* M  = (const float*)d_in[2];   // [8, 8]
    const float* M0 = (const float*)d_in[3];   // [8, 8]
    float* out = (float*)d_out;                // [T, N, 8]

    const int N = in_sizes[0] / MS;            // 16384
    const int T = in_sizes[1];                 // 512

    dim3 grid(N / ROWS_B, T / TB_T);           // (64, 32) = 2048 blocks
    fused_kernel<<<grid, THREADS>>>(x, t, M, M0, out, N);
}

// round 15
// speedup vs baseline: 1.2000x; 1.2000x over previous
#include <cuda_runtime.h>
#include <cstdint>

// ---------------------------------------------------------------------------
// LinearFlow: out[t,n,i] = sum_j expm(t_k * A)[i,j] * x[n,j]
//   A = 0.5*((M+M0) - (M+M0)^T), 8x8 skew-symmetric, ||tA|| <~ 0.15
//
// R14: PERSISTENT version of the proven R10 kernel.
//   TMA-epilogue experiment (R13) falsified: bar.sync-serialized bulk stores
//   gave 57 us / DRAM 47%. Warp-level streaming STG.128 is the right path.
//   This round removes chip-level scheduling waste instead:
//     - 740 CTAs (148 SMs x 5 resident) persistently stride over 2048 tiles
//       -> no wave transitions, no last-wave quantization tail.
//   Inner loop identical to R10: register-resident Taylor expm per tile,
//   i-pair f32x2 accumulators == output float4s, 1 LDS.128 per j,
//   2 rows/lane, 512 B coalesced streaming stores.
// ---------------------------------------------------------------------------

#define MS        8
#define TB_T      16     // t-values per tile
#define ROWS_B    256    // n-rows per tile (8 warps x 32 rows)
#define THREADS   256
#define KTERMS    10     // Taylor order; ||tA||<=0.15 -> error ~1e-17
#define GRID_P    740    // 148 SMs x 5 CTAs

// ---- f32x2 helpers ---------------------------------------------------------
__device__ __forceinline__ unsigned long long pack2(float lo, float hi) {
    unsigned long long r;
    asm("mov.b64 %0, {%1, %2};" : "=l"(r) : "f"(lo), "f"(hi));
    return r;
}
__device__ __forceinline__ unsigned long long fma2(unsigned long long a,
                                                   unsigned long long b,
                                                   unsigned long long c) {
    unsigned long long d;
    asm("fma.rn.f32x2 %0, %1, %2, %3;" : "=l"(d) : "l"(a), "l"(b), "l"(c));
    return d;
}
__device__ __forceinline__ void stcs_v2u64(void* p, unsigned long long a,
                                           unsigned long long b) {
    asm volatile("st.global.cs.v2.u64 [%0], {%1, %2};"
                 :: "l"(p), "l"(a), "l"(b) : "memory");
}

// ---------------------------------------------------------------------------
__global__ void __launch_bounds__(THREADS, 5)
fused_kernel(const float* __restrict__ x,
             const float* __restrict__ t,
             const float* __restrict__ M,
             const float* __restrict__ M0,
             float* __restrict__ out,
             int N, int T) {
    __shared__ float sAskew[64];                   // unscaled skew(A)
    __shared__ unsigned long long sE[TB_T * 32];   // 4 KB packed E

    const int tid = threadIdx.x;

    // ---- stage A_skew once ----
    if (tid < 64) {
        const int i = tid >> 3, j = tid & 7;
        sAskew[tid] = 0.5f * ((M[i * 8 + j] + M0[i * 8 + j]) -
                              (M[j * 8 + i] + M0[j * 8 + i]));
    }

    const int warp = tid >> 5;
    const int lane = tid & 31;
    const int h    = lane & 1;
    const int lrA  = warp * 32 + (lane >> 1);      // local row A in [0,256)

    const int nx = N / ROWS_B;                     // tiles along n (64)
    const int nt = (N / ROWS_B) * (T / TB_T);      // total tiles (2048)
    const size_t f4step = (size_t)2 * N;           // float4 per t-plane
    ulonglong2* outv = reinterpret_cast<ulonglong2*>(out);
    const unsigned long long* eB = sE + 2 * h;     // p-offset = 2h

    __syncthreads();                               // sAskew ready

    for (int tau = blockIdx.x; tau < nt; tau += GRID_P) {
        const int bx    = tau % nx;
        const int tbase = (tau / nx) * TB_T;
        const int rb    = bx * ROWS_B;
        const int rowA  = rb + lrA;
        const int rowB  = rowA + 16;

        // ---- load x rows (L2-hot after first pass), duplicate-packed ----
        unsigned long long xA[8], xB[8];
        {
            const float4* xpA = reinterpret_cast<const float4*>(x) + (size_t)rowA * 2;
            const float4* xpB = reinterpret_cast<const float4*>(x) + (size_t)rowB * 2;
            float4 a0 = xpA[0], a1 = xpA[1], b0 = xpB[0], b1 = xpB[1];
            xA[0] = pack2(a0.x, a0.x);  xA[1] = pack2(a0.y, a0.y);
            xA[2] = pack2(a0.z, a0.z);  xA[3] = pack2(a0.w, a0.w);
            xA[4] = pack2(a1.x, a1.x);  xA[5] = pack2(a1.y, a1.y);
            xA[6] = pack2(a1.z, a1.z);  xA[7] = pack2(a1.w, a1.w);
            xB[0] = pack2(b0.x, b0.x);  xB[1] = pack2(b0.y, b0.y);
            xB[2] = pack2(b0.z, b0.z);  xB[3] = pack2(b0.w, b0.w);
            xB[4] = pack2(b1.x, b1.x);  xB[5] = pack2(b1.y, b1.y);
            xB[6] = pack2(b1.z, b1.z);  xB[7] = pack2(b1.w, b1.w);
        }

        // ---- wait until all warps finished reading previous tile's sE ----
        __syncthreads();

        // ---- Taylor expm: thread (tl, i) owns row i for t-slot tl ----
        if (tid < TB_T * 8) {
            const int tl = tid >> 3;
            const int i  = tid & 7;
            const float tv = t[tbase + tl];

            float r[8], acc[8];
            #pragma unroll
            for (int j = 0; j < 8; j++) {
                r[j]   = tv * sAskew[i * 8 + j];
                acc[j] = ((i == j) ? 1.0f : 0.0f) + r[j];
            }
            #pragma unroll
            for (int k = 2; k <= KTERMS; k++) {
                float tmp[8];
                #pragma unroll
                for (int j = 0; j < 8; j++) {
                    float c = 0.0f;
                    #pragma unroll
                    for (int m = 0; m < 8; m++)
                        c = fmaf(r[m], sAskew[m * 8 + j], c);
                    tmp[j] = c;
                }
                const float s = tv * (1.0f / (float)k);
                #pragma unroll
                for (int j = 0; j < 8; j++) {
                    r[j] = tmp[j] * s;
                    acc[j] += r[j];
                }
            }
            // packed: float slot = (tl*32 + j*4 + (i>>1))*2 + (i&1)
            float* fE = reinterpret_cast<float*>(sE);
            #pragma unroll
            for (int j = 0; j < 8; j++)
                fE[(tl * 32 + j * 4 + (i >> 1)) * 2 + (i & 1)] = acc[j];
        }
        __syncthreads();   // sE ready

        // ---- stream out = E @ x for this tile ----
        const size_t fA = (size_t)rowA * 2 + h;    // f4 index within t-plane
        size_t base = (size_t)tbase * f4step;

        #pragma unroll 4
        for (int tl = 0; tl < TB_T; tl++) {
            const unsigned long long* e = eB + tl * 32;
            unsigned long long oA01 = 0ull, oA23 = 0ull, oB01 = 0ull, oB23 = 0ull;

            #pragma unroll
            for (int j = 0; j < 8; j++) {
                // one LDS.128 per j: E i-pairs (4h,4h+1) and (4h+2,4h+3)
                ulonglong2 ep = *reinterpret_cast<const ulonglong2*>(e + j * 4);
                oA01 = fma2(ep.x, xA[j], oA01);
                oA23 = fma2(ep.y, xA[j], oA23);
                oB01 = fma2(ep.x, xB[j], oB01);
                oB23 = fma2(ep.y, xB[j], oB23);
            }

            // accumulators are already the float4 outputs [4h..4h+3]
            stcs_v2u64(outv + base + fA,      oA01, oA23);
            stcs_v2u64(outv + base + fA + 32, oB01, oB23);  // rowB = rowA+16
            base += f4step;
        }
    }
}

// ---------------------------------------------------------------------------
extern "C" void kernel_launch(void* const* d_in, const int* in_sizes, int n_in,
                              void* d_out, int out_size) {
    const float* x  = (const float*)d_in[0];   // [N, 8]
    const float* t  = (const float*)d_in[1];   // [T]
    const float* M  = (const float*)d_in[2];   // [8, 8]
    const float* M0 = (const float*)d_in[3];   // [8, 8]
    float* out = (float*)d_out;                // [T, N, 8]

    const int N = in_sizes[0] / MS;            // 16384
    const int T = in_sizes[1];                 // 512

    fused_kernel<<<GRID_P, THREADS>>>(x, t, M, M0, out, N, T);
}

// round 16
// speedup vs baseline: 1.2179x; 1.0149x over previous
#include <cuda_runtime.h>
#include <cstdint>

// ---------------------------------------------------------------------------
// LinearFlow: out[t,n,i] = sum_j expm(t_k * A)[i,j] * x[n,j]
//   A = 0.5*((M+M0) - (M+M0)^T), 8x8 skew-symmetric, ||tA|| <~ 0.15
//
// R15 = R10 (best: 43.5 us) + occupancy pin.
//   Falsified so far: TMA bulk epilogue (R13: 57us), persistent grid
//   (R14: 48us), wave-granularity scaling (R10: flat). R10's profile shows
//   nothing saturated but occ reg-capped at 40/64 warps (48 regs).
//   Single change: __launch_bounds__(256, 6) -> 42 regs -> 6 CTA/SM,
//   48 warps (+20% resident latency-hiding).
//   Proven structure kept: fused register-resident Taylor expm prologue,
//   i-pair f32x2 accumulators == output float4s, 1 LDS.128 per j,
//   2 rows/lane, 512 B coalesced streaming (.cs) stores, 2048-CTA grid.
// ---------------------------------------------------------------------------

#define MS        8
#define TB_T      16     // t-values per block
#define ROWS_B    256    // n-rows per block (8 warps x 32 rows)
#define THREADS   256
#define KTERMS    10     // Taylor order; ||tA||<=0.15 -> error ~1e-17

// ---- f32x2 helpers ---------------------------------------------------------
__device__ __forceinline__ unsigned long long pack2(float lo, float hi) {
    unsigned long long r;
    asm("mov.b64 %0, {%1, %2};" : "=l"(r) : "f"(lo), "f"(hi));
    return r;
}
__device__ __forceinline__ unsigned long long fma2(unsigned long long a,
                                                   unsigned long long b,
                                                   unsigned long long c) {
    unsigned long long d;
    asm("fma.rn.f32x2 %0, %1, %2, %3;" : "=l"(d) : "l"(a), "l"(b), "l"(c));
    return d;
}
__device__ __forceinline__ void stcs_v2u64(void* p, unsigned long long a,
                                           unsigned long long b) {
    asm volatile("st.global.cs.v2.u64 [%0], {%1, %2};"
                 :: "l"(p), "l"(a), "l"(b) : "memory");
}

// ---------------------------------------------------------------------------
__global__ void __launch_bounds__(THREADS, 6)
fused_kernel(const float* __restrict__ x,
             const float* __restrict__ t,
             const float* __restrict__ M,
             const float* __restrict__ M0,
             float* __restrict__ out,
             int N) {
    __shared__ float sAskew[64];                   // unscaled skew(A)
    __shared__ unsigned long long sE[TB_T * 32];   // 4 KB packed E

    const int tid   = threadIdx.x;
    const int tbase = blockIdx.y * TB_T;

    // ---- stage A_skew (tiny, L2-resident after first block) ----
    if (tid < 64) {
        const int i = tid >> 3, j = tid & 7;
        sAskew[tid] = 0.5f * ((M[i * 8 + j] + M0[i * 8 + j]) -
                              (M[j * 8 + i] + M0[j * 8 + i]));
    }
    __syncthreads();

    // ---- load x rows (all threads; independent of sE) ----
    const int warp = tid >> 5;
    const int lane = tid & 31;
    const int h    = lane & 1;
    const int rb   = blockIdx.x * ROWS_B + warp * 32;
    const int rowA = rb + (lane >> 1);
    const int rowB = rowA + 16;

    unsigned long long xA[8], xB[8];
    {
        const float4* xpA = reinterpret_cast<const float4*>(x) + (size_t)rowA * 2;
        const float4* xpB = reinterpret_cast<const float4*>(x) + (size_t)rowB * 2;
        float4 a0 = xpA[0], a1 = xpA[1], b0 = xpB[0], b1 = xpB[1];
        xA[0] = pack2(a0.x, a0.x);  xA[1] = pack2(a0.y, a0.y);
        xA[2] = pack2(a0.z, a0.z);  xA[3] = pack2(a0.w, a0.w);
        xA[4] = pack2(a1.x, a1.x);  xA[5] = pack2(a1.y, a1.y);
        xA[6] = pack2(a1.z, a1.z);  xA[7] = pack2(a1.w, a1.w);
        xB[0] = pack2(b0.x, b0.x);  xB[1] = pack2(b0.y, b0.y);
        xB[2] = pack2(b0.z, b0.z);  xB[3] = pack2(b0.w, b0.w);
        xB[4] = pack2(b1.x, b1.x);  xB[5] = pack2(b1.y, b1.y);
        xB[6] = pack2(b1.z, b1.z);  xB[7] = pack2(b1.w, b1.w);
    }

    // ---- Taylor expm prologue: thread (tl, i) owns row i for t-slot tl ----
    // row_1 = tv * Askew[i][:]; row_k = (row_{k-1} @ Askew) * tv/k;
    // E row = e_i + sum_k row_k.  No syncs inside the loop.
    if (tid < TB_T * 8) {
        const int tl = tid >> 3;
        const int i  = tid & 7;
        const float tv = t[tbase + tl];

        float r[8], acc[8];
        #pragma unroll
        for (int j = 0; j < 8; j++) {
            r[j]   = tv * sAskew[i * 8 + j];
            acc[j] = ((i == j) ? 1.0f : 0.0f) + r[j];
        }
        #pragma unroll
        for (int k = 2; k <= KTERMS; k++) {
            float tmp[8];
            #pragma unroll
            for (int j = 0; j < 8; j++) {
                float c = 0.0f;
                #pragma unroll
                for (int m = 0; m < 8; m++)
                    c = fmaf(r[m], sAskew[m * 8 + j], c);
                tmp[j] = c;
            }
            const float s = tv * (1.0f / (float)k);
            #pragma unroll
            for (int j = 0; j < 8; j++) {
                r[j] = tmp[j] * s;
                acc[j] += r[j];
            }
        }
        // write packed: float slot = (tl*32 + j*4 + (i>>1))*2 + (i&1)
        float* fE = reinterpret_cast<float*>(sE);
        #pragma unroll
        for (int j = 0; j < 8; j++)
            fE[(tl * 32 + j * 4 + (i >> 1)) * 2 + (i & 1)] = acc[j];
    }
    __syncthreads();

    // ---- main loop: stream out = E @ x ----
    const size_t fA     = (size_t)rowA * 2 + h;        // f4 index within t-plane
    const size_t f4step = (size_t)2 * N;               // f4 per t-plane
    size_t base = (size_t)tbase * f4step;
    ulonglong2* outv = reinterpret_cast<ulonglong2*>(out);

    const unsigned long long* eB = sE + 2 * h;         // p-offset = 2h

    #pragma unroll 4
    for (int tl = 0; tl < TB_T; tl++) {
        const unsigned long long* e = eB + tl * 32;
        unsigned long long oA01 = 0ull, oA23 = 0ull, oB01 = 0ull, oB23 = 0ull;

        #pragma unroll
        for (int j = 0; j < 8; j++) {
            // one LDS.128 per j: E i-pairs (4h,4h+1) and (4h+2,4h+3)
            ulonglong2 ep = *reinterpret_cast<const ulonglong2*>(e + j * 4);
            oA01 = fma2(ep.x, xA[j], oA01);
            oA23 = fma2(ep.y, xA[j], oA23);
            oB01 = fma2(ep.x, xB[j], oB01);
            oB23 = fma2(ep.y, xB[j], oB23);
        }

        // accumulators are already the float4 outputs [4h..4h+3]
        stcs_v2u64(outv + base + fA,      oA01, oA23);
        stcs_v2u64(outv + base + fA + 32, oB01, oB23);  // rowB = rowA+16
        base += f4step;
    }
}

// ---------------------------------------------------------------------------
extern "C" void kernel_launch(void* const* d_in, const int* in_sizes, int n_in,
                              void* d_out, int out_size) {
    const float* x  = (const float*)d_in[0];   // [N, 8]
    const float* t  = (const float*)d_in[1];   // [T]
    const float* M  = (const float*)d_in[2];   // [8, 8]
    const float* M0 = (const float*)d_in[3];   // [8, 8]
    float* out = (float*)d_out;                // [T, N, 8]

    const int N = in_sizes[0] / MS;            // 16384
    const int T = in_sizes[1];                 // 512

    dim3 grid(N / ROWS_B, T / TB_T);           // (64, 32) = 2048 blocks
    fused_kernel<<<grid, THREADS>>>(x, t, M, M0, out, N);
}